// round 5
// baseline (speedup 1.0000x reference)
#include <cuda_runtime.h>
#include <math.h>
#include <stdint.h>

// BlurredNoise via legacy mma.sync tf32 (m16n8k8) implicit GEMM, 3xTF32 split.
// R5: pre-split X into smem {hi,lo} pairs, pass-outer MMA ordering (dep dist 4),
// conflict-free B stride 36, double-buffered B, 2 CTAs/SM.

#define KS      5000
#define IN_SEQ  9095
#define T_OUT   4096
#define NFILT   128
#define NROWS   16
#define NG      4
#define NF      32      // filters per group (GEMM N)
#define MT      512     // t per CTA (GEMM M)
#define THREADS 256
#define KB      32      // taps per staged chunk
#define BSTR    36      // smem floats per filter row: (4r+cc)%32 conflict-free
#define SX_LEN  5540    // >= 32*157 + 511 + slack
#define BCHUNK  (NF * BSTR)   // 1152 floats per (buf, hi/lo)

struct KloArr { int v[NG]; };

__device__ __forceinline__ void tf32_split(float x, uint32_t& h, float& l) {
    uint32_t xi = __float_as_uint(x);
    h = (xi + 0x1000u) & 0xFFFFE000u;          // RN to tf32 (11-bit mantissa)
    l = x - __uint_as_float(h);                // exact residual
}

__device__ __forceinline__ void mma_tf32(float* d, const uint32_t* a,
                                         uint32_t b0, uint32_t b1) {
    asm volatile(
        "mma.sync.aligned.m16n8k8.row.col.f32.tf32.tf32.f32 "
        "{%0,%1,%2,%3}, {%4,%5,%6,%7}, {%8,%9}, {%0,%1,%2,%3};"
        : "+f"(d[0]), "+f"(d[1]), "+f"(d[2]), "+f"(d[3])
        : "r"(a[0]), "r"(a[1]), "r"(a[2]), "r"(a[3]), "r"(b0), "r"(b1));
}

extern __shared__ float smem_dyn[];

__global__ __launch_bounds__(THREADS, 2)
void blur_mma_kernel(const float* __restrict__ noise,
                     const float* __restrict__ filt,
                     const float* __restrict__ scale,
                     float* __restrict__ out,
                     KloArr klo_arr)
{
    float2* sXp = reinterpret_cast<float2*>(smem_dyn);     // SX_LEN pairs {hi,lo}
    float*  sB  = smem_dyn + 2 * SX_LEN;                   // [buf][hi/lo][BCHUNK]
    float*  ss  = sB + 4 * BCHUNK;                         // NF scales

    const int tid  = threadIdx.x;
    const int g    = (NG - 1) - blockIdx.x;     // heavy group first
    const int tb   = blockIdx.y;                // t tile 0..7
    const int row  = blockIdx.z;                // 0..15

    const int t0   = tb * MT;
    const int f0   = g * NF;
    const int klo  = klo_arr.v[g];
    const int nch  = (KS - klo + KB - 1) / KB;

    // Stage x window: split once into {hi,lo} pairs
    {
        const int gbase = t0 + klo;
        const float* xrow = noise + (size_t)row * IN_SEQ;
        for (int i = tid; i < SX_LEN; i += THREADS) {
            const int gi = gbase + i;
            float x = (gi < IN_SEQ) ? xrow[gi] : 0.0f;
            uint32_t h; float l;
            tf32_split(x, h, l);
            sXp[i] = make_float2(__uint_as_float(h), l);
        }
        if (tid < NF) ss[tid] = scale[f0 + tid];
    }

    const int lane = tid & 31;
    const int w    = tid >> 5;
    const int r    = lane >> 2;      // groupID
    const int cc   = lane & 3;       // threadID in group
    const int mb   = w * 64;         // warp m-base within CTA

    // B staging coords for this thread
    const int bf = tid >> 3;         // filter 0..31
    const int bq = tid & 7;          // float4 within chunk

    float acc[4][4][4];
#pragma unroll
    for (int mt = 0; mt < 4; ++mt)
#pragma unroll
        for (int nt = 0; nt < 4; ++nt)
#pragma unroll
            for (int j = 0; j < 4; ++j)
                acc[mt][nt][j] = 0.0f;

    // --- B prefetch/stage helpers (inlined manually) ---
    const float* bgsrc = filt + (size_t)(f0 + bf) * KS;

    auto ldgB = [&](int ch) -> float4 {
        const int k = klo + ch * KB + 4 * bq;
        if (k < KS) return *reinterpret_cast<const float4*>(bgsrc + k);
        return make_float4(0.f, 0.f, 0.f, 0.f);
    };
    auto stsB = [&](int ch, float4 v) {
        float4 hv, lv; uint32_t hb;
        tf32_split(v.x, hb, lv.x); hv.x = __uint_as_float(hb);
        tf32_split(v.y, hb, lv.y); hv.y = __uint_as_float(hb);
        tf32_split(v.z, hb, lv.z); hv.z = __uint_as_float(hb);
        tf32_split(v.w, hb, lv.w); hv.w = __uint_as_float(hb);
        float* dsth = sB + ((ch & 1) * 2 + 0) * BCHUNK + bf * BSTR + 4 * bq;
        float* dstl = sB + ((ch & 1) * 2 + 1) * BCHUNK + bf * BSTR + 4 * bq;
        *reinterpret_cast<float4*>(dsth) = hv;
        *reinterpret_cast<float4*>(dstl) = lv;
    };

    stsB(0, ldgB(0));
    __syncthreads();

    for (int ch = 0; ch < nch; ++ch) {
        float4 vnext;
        const bool more = (ch + 1) < nch;
        if (more) vnext = ldgB(ch + 1);        // overlap LDG with MMAs

        const float* sBh = sB + ((ch & 1) * 2 + 0) * BCHUNK;
        const float* sBl = sB + ((ch & 1) * 2 + 1) * BCHUNK;

#pragma unroll
        for (int s = 0; s < 4; ++s) {          // k8 steps within chunk
            const int kloc = ch * KB + s * 8;

            // A fragments: one LDS.64 per element (pre-split)
            uint32_t ah[4][4], al[4][4];
            const int ib0 = mb + r + cc + kloc;
#pragma unroll
            for (int mt = 0; mt < 4; ++mt) {
                const int ib = ib0 + mt * 16;
                const int off[4] = {0, 8, 4, 12};
#pragma unroll
                for (int j = 0; j < 4; ++j) {
                    float2 v = sXp[ib + off[j]];
                    ah[mt][j] = __float_as_uint(v.x);
                    al[mt][j] = __float_as_uint(v.y);
                }
            }

#pragma unroll
            for (int nt = 0; nt < 4; ++nt) {
                const int ba = (nt * 8 + r) * BSTR + s * 8 + cc;
                const uint32_t bh0 = __float_as_uint(sBh[ba]);
                const uint32_t bh1 = __float_as_uint(sBh[ba + 4]);
                const uint32_t bl0 = __float_as_uint(sBl[ba]);
                const uint32_t bl1 = __float_as_uint(sBl[ba + 4]);
                // pass-outer: dependent MMAs on same acc are 4 apart
#pragma unroll
                for (int mt = 0; mt < 4; ++mt)
                    mma_tf32(acc[mt][nt], ah[mt], bh0, bh1);   // hi*hi
#pragma unroll
                for (int mt = 0; mt < 4; ++mt)
                    mma_tf32(acc[mt][nt], ah[mt], bl0, bl1);   // hi*lo
#pragma unroll
                for (int mt = 0; mt < 4; ++mt)
                    mma_tf32(acc[mt][nt], al[mt], bh0, bh1);   // lo*hi
            }
        }

        if (more) stsB(ch + 1, vnext);
        __syncthreads();
    }

    // Epilogue: scale + scattered stores
    // d frag: c0:(r, 2c) c1:(r, 2c+1) c2:(r+8, 2c) c3:(r+8, 2c+1)
#pragma unroll
    for (int nt = 0; nt < 4; ++nt) {
        const int fA = nt * 8 + 2 * cc;
        const float s0 = ss[fA];
        const float s1 = ss[fA + 1];
        float* o0 = out + ((size_t)row * NFILT + f0 + fA) * T_OUT + t0;
        float* o1 = o0 + T_OUT;
#pragma unroll
        for (int mt = 0; mt < 4; ++mt) {
            const int t = mb + mt * 16 + r;
            o0[t]     = acc[mt][nt][0] * s0;
            o1[t]     = acc[mt][nt][1] * s1;
            o0[t + 8] = acc[mt][nt][2] * s0;
            o1[t + 8] = acc[mt][nt][3] * s1;
        }
    }
}

extern "C" void kernel_launch(void* const* d_in, const int* in_sizes, int n_in,
                              void* d_out, int out_size)
{
    const float* noise = (const float*)d_in[0];   // (2,8,9095)
    const float* filt  = (const float*)d_in[1];   // (128,5000)
    const float* scale = (const float*)d_in[2];   // (1,128,1)
    float* out = (float*)d_out;                   // (2,1024,4096)

    KloArr ka;
    const double l0 = log2(250.0), l1 = log2(10000.0);
    for (int g = 0; g < NG; ++g) {
        const int i = NF * g + (NF - 1);           // longest filter in group
        double sr = exp2(l0 + (l1 - l0) * (double)i / 127.0);
        if (sr < 250.0)   sr = 250.0;
        if (sr > 10000.0) sr = 10000.0;
        const int taps = (int)ceil(sr * 0.5);
        int klo = KS - taps - 8;
        if (klo < 0) klo = 0;
        klo &= ~(KB - 1);
        ka.v[g] = klo;
    }

    const int smem_bytes = (2 * SX_LEN + 4 * BCHUNK + NF) * (int)sizeof(float);
    cudaFuncSetAttribute(blur_mma_kernel,
                         cudaFuncAttributeMaxDynamicSharedMemorySize, smem_bytes);

    dim3 grid(NG, T_OUT / MT, NROWS);             // (4, 8, 16) = 512 CTAs
    blur_mma_kernel<<<grid, THREADS, smem_bytes>>>(noise, filt, scale, out, ka);
}

// round 7
// speedup vs baseline: 2.0209x; 2.0209x over previous
#include <cuda_runtime.h>
#include <math.h>
#include <stdint.h>

// BlurredNoise via legacy mma.sync tf32 (m16n8k8) implicit GEMM, 2-pass split.
// D[m=t, n=filter] = sum_k x[t0+m+k] * filt[f0+n, k], k in [klo_g, 5000)
// x split into tf32 hi+lo (in registers), f rounded to tf32 (hi only):
//   x*f ~= xh*fh + xl*fh   (aggregate error ~3e-4, gate 1e-3)
// CTA: 128 threads / 4 warps, MT=256 t, NF=32 filters. Warp tile m64 n32.
// R7 fix: exact sX window length (R6 overflowed 15 floats into sBh).

#define KS      5000
#define IN_SEQ  9095
#define T_OUT   4096
#define NFILT   128
#define NROWS   16
#define NG      4
#define NF      32      // filters per group (GEMM N)
#define MT      256     // t per CTA (GEMM M)
#define THREADS 128
#define KB      32      // taps per staged chunk
#define BSTR    36      // smem floats per filter row: (4r+cc)%32 conflict-free
#define SX_LEN  5280    // max wlen = 32*157 + 255 = 5279
#define BCHUNK  (NF * BSTR)   // 1152 floats per buffer

struct KloArr { int v[NG]; };

__device__ __forceinline__ void tf32_split(float x, uint32_t& h, float& l) {
    uint32_t xi = __float_as_uint(x);
    h = (xi + 0x1000u) & 0xFFFFE000u;          // RN to tf32 (11-bit mantissa)
    l = x - __uint_as_float(h);                // exact residual
}
__device__ __forceinline__ uint32_t tf32_rn(float x) {
    return (__float_as_uint(x) + 0x1000u) & 0xFFFFE000u;
}

__device__ __forceinline__ void mma_tf32(float* d, const uint32_t* a,
                                         uint32_t b0, uint32_t b1) {
    asm volatile(
        "mma.sync.aligned.m16n8k8.row.col.f32.tf32.tf32.f32 "
        "{%0,%1,%2,%3}, {%4,%5,%6,%7}, {%8,%9}, {%0,%1,%2,%3};"
        : "+f"(d[0]), "+f"(d[1]), "+f"(d[2]), "+f"(d[3])
        : "r"(a[0]), "r"(a[1]), "r"(a[2]), "r"(a[3]), "r"(b0), "r"(b1));
}

__global__ __launch_bounds__(THREADS)
void blur_mma_kernel(const float* __restrict__ noise,
                     const float* __restrict__ filt,
                     const float* __restrict__ scale,
                     float* __restrict__ out,
                     KloArr klo_arr)
{
    __shared__ float sX[SX_LEN];
    __shared__ float sBh[2][BCHUNK];
    __shared__ float ss[NF];

    const int tid  = threadIdx.x;
    const int g    = (NG - 1) - blockIdx.x;     // heavy group first
    const int tb   = blockIdx.y;                // t tile 0..15
    const int row  = blockIdx.z;                // 0..15

    const int t0   = tb * MT;
    const int f0   = g * NF;
    const int klo  = klo_arr.v[g];
    const int nch  = (KS - klo + KB - 1) / KB;

    // Stage x window (fp32, split later in registers) + scales.
    // Max index read by A fragments: KB*nch + MT - 2 + 12... = KB*nch + MT - 2;
    // wlen = KB*nch + MT - 1 covers it exactly and fits SX_LEN.
    {
        const int wlen = KB * nch + MT - 1;
        const int gbase = t0 + klo;
        const float* xrow = noise + (size_t)row * IN_SEQ;
        for (int i = tid; i < wlen; i += THREADS) {
            const int gi = gbase + i;
            sX[i] = (gi < IN_SEQ) ? xrow[gi] : 0.0f;
        }
        if (tid < NF) ss[tid] = scale[f0 + tid];
    }

    const int lane = tid & 31;
    const int w    = tid >> 5;
    const int r    = lane >> 2;      // groupID
    const int cc   = lane & 3;       // threadID in group
    const int mb   = w * 64;         // warp m-base within CTA

    // B staging coords: 128 threads stage 32x32 chunk, one float8 per thread
    const int bf = tid >> 2;         // filter 0..31
    const int bq = tid & 3;          // which float8
    const float* bgsrc = filt + (size_t)(f0 + bf) * KS;

    float acc[4][4][4];
#pragma unroll
    for (int mt = 0; mt < 4; ++mt)
#pragma unroll
        for (int nt = 0; nt < 4; ++nt)
#pragma unroll
            for (int j = 0; j < 4; ++j)
                acc[mt][nt][j] = 0.0f;

    auto ldgB = [&](int ch, float4& v0, float4& v1) {
        const int k = klo + ch * KB + 8 * bq;
        if (k < KS) {   // k multiple of 8 and KS = 8*625, so k<KS => k+8<=KS
            v0 = *reinterpret_cast<const float4*>(bgsrc + k);
            v1 = *reinterpret_cast<const float4*>(bgsrc + k + 4);
        } else {
            v0 = v1 = make_float4(0.f, 0.f, 0.f, 0.f);
        }
    };
    auto stsB = [&](int ch, float4 v0, float4 v1) {
        uint4 h0, h1;
        h0.x = tf32_rn(v0.x); h0.y = tf32_rn(v0.y);
        h0.z = tf32_rn(v0.z); h0.w = tf32_rn(v0.w);
        h1.x = tf32_rn(v1.x); h1.y = tf32_rn(v1.y);
        h1.z = tf32_rn(v1.z); h1.w = tf32_rn(v1.w);
        float* dst = &sBh[ch & 1][bf * BSTR + 8 * bq];
        *reinterpret_cast<uint4*>(dst)     = h0;
        *reinterpret_cast<uint4*>(dst + 4) = h1;
    };

    {
        float4 a0, a1;
        ldgB(0, a0, a1);
        stsB(0, a0, a1);
    }
    __syncthreads();

    for (int ch = 0; ch < nch; ++ch) {
        float4 p0, p1;
        const bool more = (ch + 1) < nch;
        if (more) ldgB(ch + 1, p0, p1);        // overlap LDG with MMAs

        const float* sB = sBh[ch & 1];

#pragma unroll
        for (int s = 0; s < 4; ++s) {          // k8 steps within chunk
            const int kloc = ch * KB + s * 8;

            // A fragments: LDS + in-register tf32 split
            uint32_t ah[4][4], al[4][4];
            const int ib0 = mb + r + cc + kloc;
#pragma unroll
            for (int mt = 0; mt < 4; ++mt) {
                const int ib = ib0 + mt * 16;
                const int off[4] = {0, 8, 4, 12};
#pragma unroll
                for (int j = 0; j < 4; ++j) {
                    float x = sX[ib + off[j]];
                    float l;
                    tf32_split(x, ah[mt][j], l);
                    al[mt][j] = __float_as_uint(l);
                }
            }

#pragma unroll
            for (int nt = 0; nt < 4; ++nt) {
                const int ba = (nt * 8 + r) * BSTR + s * 8 + cc;
                const uint32_t bh0 = __float_as_uint(sB[ba]);
                const uint32_t bh1 = __float_as_uint(sB[ba + 4]);
                // pass-outer: dependent MMAs on same acc are 4 apart
#pragma unroll
                for (int mt = 0; mt < 4; ++mt)
                    mma_tf32(acc[mt][nt], ah[mt], bh0, bh1);   // xh*fh
#pragma unroll
                for (int mt = 0; mt < 4; ++mt)
                    mma_tf32(acc[mt][nt], al[mt], bh0, bh1);   // xl*fh
            }
        }

        if (more) stsB(ch + 1, p0, p1);
        __syncthreads();
    }

    // Epilogue: scale + scattered stores
    // d frag: c0:(r, 2c) c1:(r, 2c+1) c2:(r+8, 2c) c3:(r+8, 2c+1)
#pragma unroll
    for (int nt = 0; nt < 4; ++nt) {
        const int fA = nt * 8 + 2 * cc;
        const float s0 = ss[fA];
        const float s1 = ss[fA + 1];
        float* o0 = out + ((size_t)row * NFILT + f0 + fA) * T_OUT + t0;
        float* o1 = o0 + T_OUT;
#pragma unroll
        for (int mt = 0; mt < 4; ++mt) {
            const int t = mb + mt * 16 + r;
            o0[t]     = acc[mt][nt][0] * s0;
            o1[t]     = acc[mt][nt][1] * s1;
            o0[t + 8] = acc[mt][nt][2] * s0;
            o1[t + 8] = acc[mt][nt][3] * s1;
        }
    }
}

extern "C" void kernel_launch(void* const* d_in, const int* in_sizes, int n_in,
                              void* d_out, int out_size)
{
    const float* noise = (const float*)d_in[0];   // (2,8,9095)
    const float* filt  = (const float*)d_in[1];   // (128,5000)
    const float* scale = (const float*)d_in[2];   // (1,128,1)
    float* out = (float*)d_out;                   // (2,1024,4096)

    KloArr ka;
    const double l0 = log2(250.0), l1 = log2(10000.0);
    for (int g = 0; g < NG; ++g) {
        const int i = NF * g + (NF - 1);           // longest filter in group
        double sr = exp2(l0 + (l1 - l0) * (double)i / 127.0);
        if (sr < 250.0)   sr = 250.0;
        if (sr > 10000.0) sr = 10000.0;
        const int taps = (int)ceil(sr * 0.5);
        int klo = KS - taps - 8;
        if (klo < 0) klo = 0;
        klo &= ~(KB - 1);
        ka.v[g] = klo;
    }

    dim3 grid(NG, T_OUT / MT, NROWS);             // (4, 16, 16) = 1024 CTAs
    blur_mma_kernel<<<grid, THREADS>>>(noise, filt, scale, out, ka);
}

// round 8
// speedup vs baseline: 2.0863x; 1.0324x over previous
#include <cuda_runtime.h>
#include <math.h>
#include <stdint.h>

// BlurredNoise via mma.sync tf32 (m16n8k8) implicit GEMM, 2-pass split.
// R8: rolling 16-slot register window for Toeplitz A fragments (2 LDS + 2
// splits per k8-step instead of 16+16), 8-phase static rotation (2 chunks
// per iteration, chunk counts rounded even, klo may be negative/zero-padded).

#define KS      5000
#define IN_SEQ  9095
#define T_OUT   4096
#define NFILT   128
#define NROWS   16
#define NG      4
#define NF      32      // filters per group (GEMM N)
#define MT      256     // t per CTA (GEMM M)
#define THREADS 128
#define KB      32      // taps per chunk
#define BSTR    36      // (4r+cc)%32 conflict-free
#define SX_LEN  5320    // >= max rolling-load index 5318
#define BCHUNK  (NF * BSTR)

struct KloArr { int v[NG]; };

__device__ __forceinline__ void tf32_split(float x, uint32_t& h, uint32_t& l) {
    uint32_t xi = __float_as_uint(x);
    h = (xi + 0x1000u) & 0xFFFFE000u;
    l = __float_as_uint(x - __uint_as_float(h));
}
__device__ __forceinline__ uint32_t tf32_rn(float x) {
    return (__float_as_uint(x) + 0x1000u) & 0xFFFFE000u;
}

__device__ __forceinline__ void mma_tf32(float* d,
                                         uint32_t a0, uint32_t a1,
                                         uint32_t a2, uint32_t a3,
                                         uint32_t b0, uint32_t b1) {
    asm volatile(
        "mma.sync.aligned.m16n8k8.row.col.f32.tf32.tf32.f32 "
        "{%0,%1,%2,%3}, {%4,%5,%6,%7}, {%8,%9}, {%0,%1,%2,%3};"
        : "+f"(d[0]), "+f"(d[1]), "+f"(d[2]), "+f"(d[3])
        : "r"(a0), "r"(a1), "r"(a2), "r"(a3), "r"(b0), "r"(b1));
}

__global__ __launch_bounds__(THREADS)
void blur_mma_kernel(const float* __restrict__ noise,
                     const float* __restrict__ filt,
                     const float* __restrict__ scale,
                     float* __restrict__ out,
                     KloArr klo_arr)
{
    __shared__ float sX[SX_LEN];
    __shared__ float sBh[2][BCHUNK];
    __shared__ float ss[NF];

    const int tid  = threadIdx.x;
    const int g    = (NG - 1) - blockIdx.x;     // heavy group first
    const int tb   = blockIdx.y;
    const int row  = blockIdx.z;

    const int t0   = tb * MT;
    const int f0   = g * NF;
    const int klo  = klo_arr.v[g];              // may be negative
    const int nch  = (KS - klo) / KB;           // even by construction
    const int niter = nch >> 1;

    // Stage x window (origin klo, zero-padded both ends) + scales
    {
        const int gbase = t0 + klo;
        const float* xrow = noise + (size_t)row * IN_SEQ;
        for (int i = tid; i < SX_LEN; i += THREADS) {
            const int gi = gbase + i;
            sX[i] = (gi >= 0 && gi < IN_SEQ) ? xrow[gi] : 0.0f;
        }
        if (tid < NF) ss[tid] = scale[f0 + tid];
    }

    const int lane = tid & 31;
    const int w    = tid >> 5;
    const int r    = lane >> 2;
    const int cc   = lane & 3;
    const int mb   = w * 64;
    const int A0   = mb + r + cc;    // thread's x base within sX

    // B staging: 128 threads, one float8 (one k8-step of one filter) each
    const int bf = tid >> 2;
    const int bq = tid & 3;
    const float* bgsrc = filt + (size_t)(f0 + bf) * KS;

    float acc[4][4][4];
#pragma unroll
    for (int mt = 0; mt < 4; ++mt)
#pragma unroll
        for (int nt = 0; nt < 4; ++nt)
#pragma unroll
            for (int j = 0; j < 4; ++j)
                acc[mt][nt][j] = 0.0f;

    auto ldgB = [&](int ch, float4& v0, float4& v1) {
        const int k = klo + ch * KB + 8 * bq;
        if (k >= 0 && k < KS) {
            v0 = *reinterpret_cast<const float4*>(bgsrc + k);
            v1 = *reinterpret_cast<const float4*>(bgsrc + k + 4);
        } else {
            v0 = v1 = make_float4(0.f, 0.f, 0.f, 0.f);
        }
    };
    auto stsB = [&](int buf, float4 v0, float4 v1) {
        uint4 h0, h1;
        h0.x = tf32_rn(v0.x); h0.y = tf32_rn(v0.y);
        h0.z = tf32_rn(v0.z); h0.w = tf32_rn(v0.w);
        h1.x = tf32_rn(v1.x); h1.y = tf32_rn(v1.y);
        h1.z = tf32_rn(v1.z); h1.w = tf32_rn(v1.w);
        float* dst = &sBh[buf][bf * BSTR + 8 * bq];
        *reinterpret_cast<uint4*>(dst)     = h0;
        *reinterpret_cast<uint4*>(dst + 4) = h1;
    };

    // Stage chunk 0
    {
        float4 a0, a1;
        ldgB(0, a0, a1);
        stsB(0, a0, a1);
    }
    __syncthreads();

    // Preload rolling window: slot j holds x[A0 + 4j], pre-split
    uint32_t Wh[16], Wl[16];
#pragma unroll
    for (int j = 0; j < 16; ++j)
        tf32_split(sX[A0 + 4 * j], Wh[j], Wl[j]);

    for (int i = 0; i < niter; ++i) {
        float4 p0, p1, q0, q1;
        ldgB(2 * i + 1, p0, p1);               // prefetch odd chunk
        const bool more = (i + 1) < niter;

        // ---- phases: p = 0..7 across the two chunks of this iteration ----
#pragma unroll
        for (int half = 0; half < 2; ++half) {
            const float* sB = sBh[half];
#pragma unroll
            for (int pp = 0; pp < 4; ++pp) {
                const int p = half * 4 + pp;
#pragma unroll
                for (int nt = 0; nt < 4; ++nt) {
                    const int ba = (nt * 8 + r) * BSTR + pp * 8 + cc;
                    const uint32_t bh0 = __float_as_uint(sB[ba]);
                    const uint32_t bh1 = __float_as_uint(sB[ba + 4]);
#pragma unroll
                    for (int mt = 0; mt < 4; ++mt)
                        mma_tf32(acc[mt][nt],
                                 Wh[(4 * mt + 0 + 2 * p) & 15],
                                 Wh[(4 * mt + 2 + 2 * p) & 15],
                                 Wh[(4 * mt + 1 + 2 * p) & 15],
                                 Wh[(4 * mt + 3 + 2 * p) & 15],
                                 bh0, bh1);
#pragma unroll
                    for (int mt = 0; mt < 4; ++mt)
                        mma_tf32(acc[mt][nt],
                                 Wl[(4 * mt + 0 + 2 * p) & 15],
                                 Wl[(4 * mt + 2 + 2 * p) & 15],
                                 Wl[(4 * mt + 1 + 2 * p) & 15],
                                 Wl[(4 * mt + 3 + 2 * p) & 15],
                                 bh0, bh1);
                }
                // Refill the two dropped slots with positions +64, +68.
                // (Reads stay < SX_LEN for every reachable phase; final-phase
                //  values are never consumed.)
                {
                    const int pos = A0 + 64 * i + 8 * p + 64;
                    tf32_split(sX[pos],     Wh[(2 * p) & 15],     Wl[(2 * p) & 15]);
                    tf32_split(sX[pos + 4], Wh[(2 * p + 1) & 15], Wl[(2 * p + 1) & 15]);
                }

                if (half == 0 && pp == 3) {
                    stsB(1, p0, p1);           // stage odd chunk
                    __syncthreads();
                    if (more) ldgB(2 * i + 2, q0, q1);
                }
            }
        }

        if (more) stsB(0, q0, q1);             // stage next even chunk
        __syncthreads();
    }

    // Epilogue: scale + scattered stores
#pragma unroll
    for (int nt = 0; nt < 4; ++nt) {
        const int fA = nt * 8 + 2 * cc;
        const float s0 = ss[fA];
        const float s1 = ss[fA + 1];
        float* o0 = out + ((size_t)row * NFILT + f0 + fA) * T_OUT + t0;
        float* o1 = o0 + T_OUT;
#pragma unroll
        for (int mt = 0; mt < 4; ++mt) {
            const int t = mb + mt * 16 + r;
            o0[t]     = acc[mt][nt][0] * s0;
            o1[t]     = acc[mt][nt][1] * s1;
            o0[t + 8] = acc[mt][nt][2] * s0;
            o1[t + 8] = acc[mt][nt][3] * s1;
        }
    }
}

extern "C" void kernel_launch(void* const* d_in, const int* in_sizes, int n_in,
                              void* d_out, int out_size)
{
    const float* noise = (const float*)d_in[0];   // (2,8,9095)
    const float* filt  = (const float*)d_in[1];   // (128,5000)
    const float* scale = (const float*)d_in[2];   // (1,128,1)
    float* out = (float*)d_out;                   // (2,1024,4096)

    KloArr ka;
    const double l0 = log2(250.0), l1 = log2(10000.0);
    for (int g = 0; g < NG; ++g) {
        const int i = NF * g + (NF - 1);           // longest filter in group
        double sr = exp2(l0 + (l1 - l0) * (double)i / 127.0);
        if (sr < 250.0)   sr = 250.0;
        if (sr > 10000.0) sr = 10000.0;
        const int taps = (int)ceil(sr * 0.5);
        int nch = (taps + 8 + KB - 1) / KB;
        if (nch & 1) nch++;                        // even: 8-phase rotation
        ka.v[g] = KS - KB * nch;                   // may be negative (zero pad)
    }

    dim3 grid(NG, T_OUT / MT, NROWS);             // (4, 16, 16) = 1024 CTAs
    blur_mma_kernel<<<grid, THREADS>>>(noise, filt, scale, out, ka);
}

// round 9
// speedup vs baseline: 4.0938x; 1.9622x over previous
#include <cuda_runtime.h>
#include <cuda_fp16.h>
#include <math.h>
#include <stdint.h>

// BlurredNoise via mma.sync fp16 (m16n8k16) implicit GEMM, 2-pass split.
// D[m=t, n=filter] = sum_k x[t0+m+k] * filt[f0+n, k]
// x split: xh = fp16(x), xl = fp16(x - xh); f rounded to fp16.
//   x*f ~= xh*fh + xl*fh  (same 10-bit mantissa as the passing tf32 kernel)
// X staged in smem as consecutive fp16 pairs sP[i] = {x[i], x[i+1]} so any
// Toeplitz A fragment is an aligned LDS.32; a1==a2 and a3(mt)==a0(mt+1)
// collapse each k16 pass to 9 loads.

#define KS      5000
#define IN_SEQ  9095
#define T_OUT   4096
#define NFILT   128
#define NROWS   16
#define NG      4
#define NF      32      // filters per group (GEMM N)
#define MT      256     // t per CTA (GEMM M)
#define THREADS 128
#define KB      32      // taps per chunk (2 k16 steps)
#define SXP_LEN 5280    // max wlen = 32*157 + 255 = 5279
#define BROW    17      // uint pairs per filter row (16 + 1 pad)
#define BCH     (NF * BROW)

struct KloArr { int v[NG]; };

__device__ __forceinline__ uint32_t packh2(float a, float b) {
    __half2 h = __halves2half2(__float2half_rn(a), __float2half_rn(b));
    return *reinterpret_cast<uint32_t*>(&h);
}

__device__ __forceinline__ void mma_f16(float* d,
                                        uint32_t a0, uint32_t a1,
                                        uint32_t a2, uint32_t a3,
                                        uint32_t b0, uint32_t b1) {
    asm volatile(
        "mma.sync.aligned.m16n8k16.row.col.f32.f16.f16.f32 "
        "{%0,%1,%2,%3}, {%4,%5,%6,%7}, {%8,%9}, {%0,%1,%2,%3};"
        : "+f"(d[0]), "+f"(d[1]), "+f"(d[2]), "+f"(d[3])
        : "r"(a0), "r"(a1), "r"(a2), "r"(a3), "r"(b0), "r"(b1));
}

__global__ __launch_bounds__(THREADS)
void blur_mma_kernel(const float* __restrict__ noise,
                     const float* __restrict__ filt,
                     const float* __restrict__ scale,
                     float* __restrict__ out,
                     KloArr klo_arr)
{
    __shared__ uint32_t sPh[SXP_LEN];   // {xh[i], xh[i+1]}
    __shared__ uint32_t sPl[SXP_LEN];   // {xl[i], xl[i+1]}
    __shared__ uint32_t sBp[2][BCH];    // fp16 filter pairs, double-buffered
    __shared__ float ss[NF];

    const int tid  = threadIdx.x;
    const int g    = (NG - 1) - blockIdx.x;     // heavy group first
    const int tb   = blockIdx.y;
    const int row  = blockIdx.z;

    const int t0   = tb * MT;
    const int f0   = g * NF;
    const int klo  = klo_arr.v[g];              // may be negative (zero pad)
    const int nch  = (KS - klo) / KB;

    // Stage x window as split fp16 pairs + scales
    {
        const int wlen = KB * nch + MT - 1;
        const int gbase = t0 + klo;
        const float* xrow = noise + (size_t)row * IN_SEQ;
        for (int i = tid; i < wlen; i += THREADS) {
            const int gi = gbase + i;
            float x0 = (gi >= 0     && gi < IN_SEQ)     ? xrow[gi]     : 0.0f;
            float x1 = (gi + 1 >= 0 && gi + 1 < IN_SEQ) ? xrow[gi + 1] : 0.0f;
            float h0 = __half2float(__float2half_rn(x0));
            float h1 = __half2float(__float2half_rn(x1));
            sPh[i] = packh2(h0, h1);
            sPl[i] = packh2(x0 - h0, x1 - h1);
        }
        if (tid < NF) ss[tid] = scale[f0 + tid];
    }

    const int lane = tid & 31;
    const int w    = tid >> 5;
    const int r    = lane >> 2;
    const int cc   = lane & 3;
    const int mb   = w * 64;
    const int A0   = mb + r + 2 * cc;   // thread A-frag base within sP

    // B staging: 128 threads, 8 taps (4 pairs) of one filter each
    const int bf = tid >> 2;
    const int bq = tid & 3;
    const float* bgsrc = filt + (size_t)(f0 + bf) * KS;

    float acc[4][4][4];
#pragma unroll
    for (int mt = 0; mt < 4; ++mt)
#pragma unroll
        for (int nt = 0; nt < 4; ++nt)
#pragma unroll
            for (int j = 0; j < 4; ++j)
                acc[mt][nt][j] = 0.0f;

    auto ldgB = [&](int ch, float4& v0, float4& v1) {
        const int k = klo + ch * KB + 8 * bq;   // k ≡ 0 (mod 8)
        if (k >= 0 && k < KS) {
            v0 = *reinterpret_cast<const float4*>(bgsrc + k);
            v1 = *reinterpret_cast<const float4*>(bgsrc + k + 4);
        } else {
            v0 = v1 = make_float4(0.f, 0.f, 0.f, 0.f);
        }
    };
    auto stsB = [&](int buf, float4 v0, float4 v1) {
        uint32_t* dst = &sBp[buf][bf * BROW + 4 * bq];
        dst[0] = packh2(v0.x, v0.y);
        dst[1] = packh2(v0.z, v0.w);
        dst[2] = packh2(v1.x, v1.y);
        dst[3] = packh2(v1.z, v1.w);
    };

    {
        float4 a0, a1;
        ldgB(0, a0, a1);
        stsB(0, a0, a1);
    }
    __syncthreads();

    for (int ch = 0; ch < nch; ++ch) {
        float4 p0, p1;
        const bool more = (ch + 1) < nch;
        if (more) ldgB(ch + 1, p0, p1);         // overlap LDG with MMAs

        const int buf = ch & 1;

#pragma unroll
        for (int s = 0; s < 2; ++s) {           // k16 steps within chunk
            const int base = A0 + ch * KB + 16 * s;

            // A fragments: 9 pair-words per pass cover all 4 m-tiles
            uint32_t wh[9], wl[9];
#pragma unroll
            for (int j = 0; j < 9; ++j) wh[j] = sPh[base + 8 * j];
#pragma unroll
            for (int j = 0; j < 9; ++j) wl[j] = sPl[base + 8 * j];

#pragma unroll
            for (int nt = 0; nt < 4; ++nt) {
                const uint32_t* brow = &sBp[buf][(nt * 8 + r) * BROW + 8 * s];
                const uint32_t b0 = brow[cc];
                const uint32_t b1 = brow[cc + 4];
#pragma unroll
                for (int mt = 0; mt < 4; ++mt)
                    mma_f16(acc[mt][nt],
                            wh[2 * mt], wh[2 * mt + 1],
                            wh[2 * mt + 1], wh[2 * mt + 2],
                            b0, b1);            // xh*fh
#pragma unroll
                for (int mt = 0; mt < 4; ++mt)
                    mma_f16(acc[mt][nt],
                            wl[2 * mt], wl[2 * mt + 1],
                            wl[2 * mt + 1], wl[2 * mt + 2],
                            b0, b1);            // xl*fh
            }
        }

        if (more) stsB(buf ^ 1, p0, p1);
        __syncthreads();
    }

    // Epilogue: scale + scattered stores
    // d frag: c0:(r, 2c) c1:(r, 2c+1) c2:(r+8, 2c) c3:(r+8, 2c+1)
#pragma unroll
    for (int nt = 0; nt < 4; ++nt) {
        const int fA = nt * 8 + 2 * cc;
        const float s0 = ss[fA];
        const float s1 = ss[fA + 1];
        float* o0 = out + ((size_t)row * NFILT + f0 + fA) * T_OUT + t0;
        float* o1 = o0 + T_OUT;
#pragma unroll
        for (int mt = 0; mt < 4; ++mt) {
            const int t = mb + mt * 16 + r;
            o0[t]     = acc[mt][nt][0] * s0;
            o1[t]     = acc[mt][nt][1] * s1;
            o0[t + 8] = acc[mt][nt][2] * s0;
            o1[t + 8] = acc[mt][nt][3] * s1;
        }
    }
}

extern "C" void kernel_launch(void* const* d_in, const int* in_sizes, int n_in,
                              void* d_out, int out_size)
{
    const float* noise = (const float*)d_in[0];   // (2,8,9095)
    const float* filt  = (const float*)d_in[1];   // (128,5000)
    const float* scale = (const float*)d_in[2];   // (1,128,1)
    float* out = (float*)d_out;                   // (2,1024,4096)

    KloArr ka;
    const double l0 = log2(250.0), l1 = log2(10000.0);
    for (int g = 0; g < NG; ++g) {
        const int i = NF * g + (NF - 1);           // longest filter in group
        double sr = exp2(l0 + (l1 - l0) * (double)i / 127.0);
        if (sr < 250.0)   sr = 250.0;
        if (sr > 10000.0) sr = 10000.0;
        const int taps = (int)ceil(sr * 0.5);
        const int nch = (taps + 8 + KB - 1) / KB;
        ka.v[g] = KS - KB * nch;                   // may be negative (zero pad)
    }

    dim3 grid(NG, T_OUT / MT, NROWS);             // (4, 16, 16) = 1024 CTAs
    blur_mma_kernel<<<grid, THREADS>>>(noise, filt, scale, out, ka);
}

// round 10
// speedup vs baseline: 4.1582x; 1.0157x over previous
#include <cuda_runtime.h>
#include <cuda_fp16.h>
#include <math.h>
#include <stdint.h>

// BlurredNoise via mma.sync fp16 (m16n8k16) implicit GEMM, 2-pass split.
// R10: per-n8-tile chunk-start (filters' zero-prefixes skipped at 8-filter
// granularity -> 26% fewer MMAs, bit-identical result).

#define KS      5000
#define IN_SEQ  9095
#define T_OUT   4096
#define NFILT   128
#define NROWS   16
#define NG      4
#define NF      32      // filters per group (GEMM N)
#define MT      256     // t per CTA (GEMM M)
#define THREADS 128
#define KB      32      // taps per chunk (2 k16 steps)
#define SXP_LEN 5280    // max wlen = 32*157 + 255 = 5279
#define BROW    17      // uint pairs per filter row (16 + 1 pad)
#define BCH     (NF * BROW)

struct StartArr { int klo[NG]; int st[NG][4]; };   // per-group klo, per-nt chunk start

__device__ __forceinline__ uint32_t packh2(float a, float b) {
    __half2 h = __halves2half2(__float2half_rn(a), __float2half_rn(b));
    return *reinterpret_cast<uint32_t*>(&h);
}

__device__ __forceinline__ void mma_f16(float* d,
                                        uint32_t a0, uint32_t a1,
                                        uint32_t a2, uint32_t a3,
                                        uint32_t b0, uint32_t b1) {
    asm volatile(
        "mma.sync.aligned.m16n8k16.row.col.f32.f16.f16.f32 "
        "{%0,%1,%2,%3}, {%4,%5,%6,%7}, {%8,%9}, {%0,%1,%2,%3};"
        : "+f"(d[0]), "+f"(d[1]), "+f"(d[2]), "+f"(d[3])
        : "r"(a0), "r"(a1), "r"(a2), "r"(a3), "r"(b0), "r"(b1));
}

__global__ __launch_bounds__(THREADS)
void blur_mma_kernel(const float* __restrict__ noise,
                     const float* __restrict__ filt,
                     const float* __restrict__ scale,
                     float* __restrict__ out,
                     StartArr sa)
{
    __shared__ uint32_t sPh[SXP_LEN];   // {xh[i], xh[i+1]}
    __shared__ uint32_t sPl[SXP_LEN];   // {xl[i], xl[i+1]}
    __shared__ uint32_t sBp[2][BCH];    // fp16 filter pairs, double-buffered
    __shared__ float ss[NF];

    const int tid  = threadIdx.x;
    const int g    = (NG - 1) - blockIdx.x;     // heavy group first
    const int tb   = blockIdx.y;
    const int row  = blockIdx.z;

    const int t0   = tb * MT;
    const int f0   = g * NF;
    const int klo  = sa.klo[g];                 // may be negative (zero pad)
    const int nch  = (KS - klo) / KB;
    const int st0  = sa.st[g][0];               // first active chunk per nt tile
    const int st1  = sa.st[g][1];
    const int st2  = sa.st[g][2];
    const int st3  = sa.st[g][3];               // == 0

    // Stage x window as split fp16 pairs + scales
    {
        const int wlen = KB * nch + MT - 1;
        const int gbase = t0 + klo;
        const float* xrow = noise + (size_t)row * IN_SEQ;
        for (int i = tid; i < wlen; i += THREADS) {
            const int gi = gbase + i;
            float x0 = (gi >= 0     && gi < IN_SEQ)     ? xrow[gi]     : 0.0f;
            float x1 = (gi + 1 >= 0 && gi + 1 < IN_SEQ) ? xrow[gi + 1] : 0.0f;
            float h0 = __half2float(__float2half_rn(x0));
            float h1 = __half2float(__float2half_rn(x1));
            sPh[i] = packh2(h0, h1);
            sPl[i] = packh2(x0 - h0, x1 - h1);
        }
        if (tid < NF) ss[tid] = scale[f0 + tid];
    }

    const int lane = tid & 31;
    const int w    = tid >> 5;
    const int r    = lane >> 2;
    const int cc   = lane & 3;
    const int mb   = w * 64;
    const int A0   = mb + r + 2 * cc;   // thread A-frag base within sP

    // B staging: 128 threads, 8 taps (4 pairs) of one filter each
    const int bf = tid >> 2;
    const int bq = tid & 3;
    const float* bgsrc = filt + (size_t)(f0 + bf) * KS;

    float acc[4][4][4];
#pragma unroll
    for (int mt = 0; mt < 4; ++mt)
#pragma unroll
        for (int nt = 0; nt < 4; ++nt)
#pragma unroll
            for (int j = 0; j < 4; ++j)
                acc[mt][nt][j] = 0.0f;

    auto ldgB = [&](int ch, float4& v0, float4& v1) {
        const int k = klo + ch * KB + 8 * bq;   // k ≡ 0 (mod 8)
        if (k >= 0 && k < KS) {
            v0 = *reinterpret_cast<const float4*>(bgsrc + k);
            v1 = *reinterpret_cast<const float4*>(bgsrc + k + 4);
        } else {
            v0 = v1 = make_float4(0.f, 0.f, 0.f, 0.f);
        }
    };
    auto stsB = [&](int buf, float4 v0, float4 v1) {
        uint32_t* dst = &sBp[buf][bf * BROW + 4 * bq];
        dst[0] = packh2(v0.x, v0.y);
        dst[1] = packh2(v0.z, v0.w);
        dst[2] = packh2(v1.x, v1.y);
        dst[3] = packh2(v1.z, v1.w);
    };

    {
        float4 a0, a1;
        ldgB(0, a0, a1);
        stsB(0, a0, a1);
    }
    __syncthreads();

    for (int ch = 0; ch < nch; ++ch) {
        float4 p0, p1;
        const bool more = (ch + 1) < nch;
        if (more) ldgB(ch + 1, p0, p1);         // overlap LDG with MMAs

        const int buf = ch & 1;
        // nt-tile activity: filters in nt tile are zero for ch < st[nt]
        const bool a0v = (ch >= st0);
        const bool a1v = (ch >= st1);
        const bool a2v = (ch >= st2);

#pragma unroll
        for (int s = 0; s < 2; ++s) {           // k16 steps within chunk
            const int base = A0 + ch * KB + 16 * s;

            // A fragments: 9 pair-words per pass cover all 4 m-tiles
            uint32_t wh[9], wl[9];
#pragma unroll
            for (int j = 0; j < 9; ++j) wh[j] = sPh[base + 8 * j];
#pragma unroll
            for (int j = 0; j < 9; ++j) wl[j] = sPl[base + 8 * j];

#pragma unroll
            for (int nt = 0; nt < 4; ++nt) {
                if (nt == 0 && !a0v) continue;
                if (nt == 1 && !a1v) continue;
                if (nt == 2 && !a2v) continue;
                const uint32_t* brow = &sBp[buf][(nt * 8 + r) * BROW + 8 * s];
                const uint32_t b0 = brow[cc];
                const uint32_t b1 = brow[cc + 4];
#pragma unroll
                for (int mt = 0; mt < 4; ++mt)
                    mma_f16(acc[mt][nt],
                            wh[2 * mt], wh[2 * mt + 1],
                            wh[2 * mt + 1], wh[2 * mt + 2],
                            b0, b1);            // xh*fh
#pragma unroll
                for (int mt = 0; mt < 4; ++mt)
                    mma_f16(acc[mt][nt],
                            wl[2 * mt], wl[2 * mt + 1],
                            wl[2 * mt + 1], wl[2 * mt + 2],
                            b0, b1);            // xl*fh
            }
        }

        if (more) stsB(buf ^ 1, p0, p1);
        __syncthreads();
    }

    // Epilogue: scale + scattered stores
    // d frag: c0:(r, 2c) c1:(r, 2c+1) c2:(r+8, 2c) c3:(r+8, 2c+1)
#pragma unroll
    for (int nt = 0; nt < 4; ++nt) {
        const int fA = nt * 8 + 2 * cc;
        const float s0 = ss[fA];
        const float s1 = ss[fA + 1];
        float* o0 = out + ((size_t)row * NFILT + f0 + fA) * T_OUT + t0;
        float* o1 = o0 + T_OUT;
#pragma unroll
        for (int mt = 0; mt < 4; ++mt) {
            const int t = mb + mt * 16 + r;
            o0[t]     = acc[mt][nt][0] * s0;
            o1[t]     = acc[mt][nt][1] * s1;
            o0[t + 8] = acc[mt][nt][2] * s0;
            o1[t + 8] = acc[mt][nt][3] * s1;
        }
    }
}

extern "C" void kernel_launch(void* const* d_in, const int* in_sizes, int n_in,
                              void* d_out, int out_size)
{
    const float* noise = (const float*)d_in[0];   // (2,8,9095)
    const float* filt  = (const float*)d_in[1];   // (128,5000)
    const float* scale = (const float*)d_in[2];   // (1,128,1)
    float* out = (float*)d_out;                   // (2,1024,4096)

    StartArr sa;
    const double l0 = log2(250.0), l1 = log2(10000.0);
    for (int g = 0; g < NG; ++g) {
        int nch_nt[4];
        for (int nt = 0; nt < 4; ++nt) {
            const int i = g * NF + nt * 8 + 7;     // longest filter in n8 tile
            double sr = exp2(l0 + (l1 - l0) * (double)i / 127.0);
            if (sr < 250.0)   sr = 250.0;
            if (sr > 10000.0) sr = 10000.0;
            const int taps = (int)ceil(sr * 0.5);
            nch_nt[nt] = (taps + 8 + KB - 1) / KB;
        }
        const int nmax = nch_nt[3];                // filters ordered by taps
        sa.klo[g] = KS - KB * nmax;                // may be negative (zero pad)
        for (int nt = 0; nt < 4; ++nt)
            sa.st[g][nt] = nmax - nch_nt[nt];
    }

    dim3 grid(NG, T_OUT / MT, NROWS);             // (4, 16, 16) = 1024 CTAs
    blur_mma_kernel<<<grid, THREADS>>>(noise, filt, scale, out, sa);
}